// round 16
// baseline (speedup 1.0000x reference)
#include <cuda_runtime.h>
#include <cstdint>

#define NPTS   500000
#define CCH    128
#define KTAPS  27
#define C4     32
#define C2     64

typedef unsigned long long ull;

// ---------- packed f32x2 helpers (dense FFMA stage 4) ----------
static __device__ __forceinline__ ull fma2(ull a, ull b, ull c) {
    ull d;
    asm("fma.rn.f32x2 %0, %1, %2, %3;" : "=l"(d) : "l"(a), "l"(b), "l"(c));
    return d;
}
static __device__ __forceinline__ ull dup2(float w) {
    ull r;
    asm("mov.b64 %0, {%1, %1};" : "=l"(r) : "f"(w));
    return r;
}
static __device__ __forceinline__ void unpack2(ull v, float& lo, float& hi) {
    asm("mov.b64 {%0, %1}, %2;" : "=f"(lo), "=f"(hi) : "l"(v));
}

// ---------- tf32 / mma / ldmatrix / cp.async helpers ----------
static __device__ __forceinline__ float rna_tf32(float f) {
    unsigned u;
    asm("cvt.rna.tf32.f32 %0, %1;" : "=r"(u) : "f"(f));
    return __uint_as_float(u);
}
static __device__ __forceinline__ void mma_tf32(float* d, const unsigned* a, const unsigned* b) {
    asm volatile(
        "mma.sync.aligned.m16n8k8.row.col.f32.tf32.tf32.f32 "
        "{%0,%1,%2,%3},{%4,%5,%6,%7},{%8,%9},{%0,%1,%2,%3};"
        : "+f"(d[0]), "+f"(d[1]), "+f"(d[2]), "+f"(d[3])
        : "r"(a[0]), "r"(a[1]), "r"(a[2]), "r"(a[3]), "r"(b[0]), "r"(b[1]));
}
static __device__ __forceinline__ void ldsm_x4(unsigned& r0, unsigned& r1,
                                               unsigned& r2, unsigned& r3, unsigned addr) {
    asm volatile("ldmatrix.sync.aligned.m8n8.x4.shared.b16 {%0,%1,%2,%3}, [%4];"
                 : "=r"(r0), "=r"(r1), "=r"(r2), "=r"(r3) : "r"(addr));
}
static __device__ __forceinline__ void cp16(unsigned dst, const void* src, unsigned sz) {
    asm volatile("cp.async.cg.shared.global [%0], [%1], 16, %2;"
                 :: "r"(dst), "l"(src), "r"(sz));
}
static __device__ __forceinline__ void cp16f(unsigned dst, const void* src) {
    asm volatile("cp.async.cg.shared.global [%0], [%1], 16;"
                 :: "r"(dst), "l"(src));
}

// ---------- static scratch ----------
__device__ float    g_h0[(size_t)NPTS * C4];   // relu(x@W00+b00), tf32-rounded
__device__ float    g_t0[(size_t)NPTS * C4];   // full precision (feeds FFMA stage4)
__device__ float    g_h1[(size_t)NPTS * C4];   // tf32-rounded
__device__ unsigned g_mbits[NPTS];             // packed 27-tap mask bits
__device__ int      g_nbrT[(size_t)KTAPS * NPTS];  // transposed neighbor table [k][p]
__device__ float    g_wt00[4   * C4 * 36];
__device__ float    g_wt01[27  * C4 * 36];
__device__ float    g_wt10[108 * C4 * 36];
__device__ float    g_wt11[27  * C2 * 36];

// ---------- mask prep: fold [N,27] int32 -> [N] bitmask ----------
__global__ void prep_mask(const int* __restrict__ mask, unsigned* __restrict__ mb,
                          int npts)
{
    const int p = blockIdx.x * blockDim.x + threadIdx.x;
    if (p < npts) {
        const int* mp = mask + (size_t)p * KTAPS;
        unsigned b = 0;
#pragma unroll
        for (int k = 0; k < KTAPS; ++k) b |= (unsigned)(mp[k] != 0) << k;
        mb[p] = b;
    }
}

// ---------- neighbor transpose: nbrT[k*N + p] = nbr[p*27 + k] ----------
__global__ void prep_nbrT(const int* __restrict__ nbr, int* __restrict__ nbrT,
                          int npts)
{
    const size_t total = (size_t)npts * KTAPS;
    for (size_t idx = (size_t)blockIdx.x * blockDim.x + threadIdx.x; idx < total;
         idx += (size_t)gridDim.x * blockDim.x) {
        const int p = (int)(idx % npts);
        const int k = (int)(idx / npts);
        nbrT[idx] = nbr[(size_t)p * KTAPS + k];
    }
}

// ---------- weight prep: round + transpose into padded [it][co][ci(36)] ----------
__global__ void prep_w(const float* __restrict__ W, float* __restrict__ Wt,
                       int ktaps, int CIN, int COUT)
{
    const int chunks = CIN / 32;
    const int total  = ktaps * chunks * COUT * 36;
    for (int idx = blockIdx.x * blockDim.x + threadIdx.x; idx < total;
         idx += gridDim.x * blockDim.x) {
        const int ci36 = idx % 36;
        const int rest = idx / 36;
        const int co   = rest % COUT;
        const int kc   = rest / COUT;
        const int cc   = kc % chunks;
        const int k    = kc / chunks;
        float v = 0.f;
        if (ci36 < 32)
            v = rna_tf32(W[((size_t)k * CIN + cc * 32 + ci36) * COUT + co]);
        Wt[idx] = v;
    }
}

// =====================================================================
// tf32 tensor-core sparse/dense conv (best-known shape: 256 threads /
// 8 warps, 128 pts/block, 1 m16-tile per warp, coalesced 8-lanes-per-row
// gather, single __syncthreads per iteration, NBUF=2 cp.async ring).
// This round: masked rows SKIP the gather cp.async entirely (no zero-fill
// write wavefronts); their A fragments are zeroed in registers via the
// per-row mask bits instead.
// =====================================================================
template<int CIN, int COUT, int KK, int NBUF, bool DENSE, bool CVT_A,
         bool RELU, bool RESID, bool ROUND_OUT>
__global__ __launch_bounds__(256)
void conv3_tc(const float* __restrict__ fin,
              const int* __restrict__ nbrT,
              const unsigned* __restrict__ mbits_arr,
              const float* __restrict__ Wt,
              const float* __restrict__ bias,
              float* __restrict__ fout, int out_stride, int out_off,
              const float* __restrict__ resid, int resid_off,
              int npts)
{
    constexpr int CHUNKS = CIN / 32;
    constexpr int ITERS  = KK * CHUNKS;
    constexpr int KSH    = (CHUNKS == 4) ? 2 : 0;   // it -> tap shift
    constexpr int NT     = COUT / 8;
    constexpr int GSTR   = 36;
    constexpr int G_ELE  = 128 * GSTR;
    constexpr int W_ELE  = COUT * 36;

    extern __shared__ float smem[];
    float* sG = smem;                      // NBUF * G_ELE
    float* sW = smem + NBUF * G_ELE;       // NBUF * W_ELE

    const int tid   = threadIdx.x;
    const int warp  = tid >> 5;
    const int lane  = tid & 31;
    const int tile0 = blockIdx.x * 128;

    const unsigned sg_u32 = (unsigned)__cvta_generic_to_shared(sG);
    const unsigned sw_u32 = (unsigned)__cvta_generic_to_shared(sW);

    // ---- gather mapping: 8 lanes per row; warp owns its 16 A-rows ----
    const int grp = lane >> 3;     // 0..3 : row subgroup
    const int sub = lane & 7;      // 0..7 : 16B slot within row
    int      pgl[4];               // global point index per served row
    int      jden[4];              // clamped dense index
    unsigned mcur[4];              // mask bits, pre-shifted (bit0 = current tap)
    unsigned dstb[4];              // SMEM dst base (buf 0)
#pragma unroll
    for (int c = 0; c < 4; ++c) {
        const int rl = warp * 16 + c * 4 + grp;
        pgl[c]  = tile0 + rl;
        jden[c] = (pgl[c] < npts) ? pgl[c] : 0;
        mcur[c] = 0;
        if (!DENSE && pgl[c] < npts) mcur[c] = mbits_arr[pgl[c]];
        dstb[c] = sg_u32 + (rl * GSTR + sub * 4) * 4;
    }

    // ---- A-fragment row masks: this thread's mma regs hold rows g, g+8 ----
    const int g_m = lane >> 2;
    unsigned mrowA0 = 0, mrowA1 = 0;
    if (!DENSE) {
        const int r0 = tile0 + warp * 16 + g_m;
        const int r1 = r0 + 8;
        if (r0 < npts) mrowA0 = mbits_arr[r0];
        if (r1 < npts) mrowA1 = mbits_arr[r1];
    }

    // ---- incremental issue state ----
    int          cc_cur = 0;
    int          ccoff  = 0;
    const int*   nbrp   = nbrT;
    const float* wsrc   = Wt;
    const float* fin_s  = fin + sub * 4;

    auto issue = [&](int buf) {
#pragma unroll
        for (int c = 0; c < 4; ++c) {
            if (DENSE) {
                const unsigned sz = (pgl[c] < npts) ? 16u : 0u;
                const float* src = fin_s + (size_t)jden[c] * CIN + ccoff;
                cp16(dstb[c] + (unsigned)(buf * G_ELE * 4), src, sz);
            } else if (mcur[c] & 1u) {
                // unmasked row: real gather; masked rows issue NOTHING
                const int j = __ldg(nbrp + pgl[c]);
                const float* src = fin_s + (size_t)j * CIN + ccoff;
                cp16(dstb[c] + (unsigned)(buf * G_ELE * 4), src, 16u);
            }
        }
        // weights: contiguous padded tile
        const unsigned wdst = sw_u32 + buf * W_ELE * 4;
        constexpr int NCH = W_ELE / 4;
#pragma unroll
        for (int i = 0; i < (NCH + 255) / 256; ++i) {
            const int idx = tid + i * 256;
            if (NCH % 256 == 0 || idx < NCH)
                cp16f(wdst + idx * 16, wsrc + idx * 4);
        }
        wsrc += W_ELE;
        if (++cc_cur == CHUNKS) {
            cc_cur = 0; ccoff = 0;
            if (!DENSE) {
                nbrp += npts;
#pragma unroll
                for (int c = 0; c < 4; ++c) mcur[c] >>= 1;
            }
        } else {
            ccoff += 32;
        }
    };

    // ---- fragment base addresses ----
    const int rowA = (lane & 7) + ((lane >> 3) & 1) * 8;
    const int colA = (lane >> 4) & 1;
    const unsigned a_base = sg_u32 + ((warp * 16 + rowA) * GSTR + colA * 4) * 4;

    const int rowB = (lane & 7) + ((lane >> 4) & 1) * 8;
    const int colB = (lane >> 3) & 1;
    unsigned b_base[NT / 2];
#pragma unroll
    for (int ntp = 0; ntp < NT / 2; ++ntp)
        b_base[ntp] = sw_u32 + ((ntp * 16 + rowB) * 36 + colB * 4) * 4;

    float acc[NT][4];
#pragma unroll
    for (int nt = 0; nt < NT; ++nt)
#pragma unroll
        for (int i = 0; i < 4; ++i) acc[nt][i] = 0.f;

    // ---- pipeline: NBUF buffers, one sync per iteration, uniform groups ----
#pragma unroll
    for (int i = 0; i < NBUF - 1; ++i) {
        if (i < ITERS) issue(i);
        asm volatile("cp.async.commit_group;");
    }

    for (int it = 0; it < ITERS; ++it) {
        asm volatile("cp.async.wait_group %0;" :: "n"(NBUF - 2));
        __syncthreads();
        {
            const int nx = it + NBUF - 1;
            if (nx < ITERS) issue(nx % NBUF);
            asm volatile("cp.async.commit_group;");
        }
        const int buf = it % NBUF;
        const unsigned goff = (unsigned)(buf * G_ELE * 4);
        const unsigned woff = (unsigned)(buf * W_ELE * 4);
        // per-tap A-row validity for this thread's fragment rows
        unsigned v0 = 1u, v1 = 1u;
        if (!DENSE) {
            const int k = it >> KSH;
            v0 = (mrowA0 >> k) & 1u;
            v1 = (mrowA1 >> k) & 1u;
        }
#pragma unroll
        for (int s = 0; s < 4; ++s) {
            unsigned A[4];
            ldsm_x4(A[0], A[1], A[2], A[3], a_base + goff + s * 32);
            if (!DENSE) {
                // regs {0,2} belong to row g, {1,3} to row g+8; zero stale rows
                A[0] = v0 ? A[0] : 0u;
                A[2] = v0 ? A[2] : 0u;
                A[1] = v1 ? A[1] : 0u;
                A[3] = v1 ? A[3] : 0u;
            }
            if (CVT_A) {
#pragma unroll
                for (int i = 0; i < 4; ++i)
                    A[i] = __float_as_uint(rna_tf32(__uint_as_float(A[i])));
            }
#pragma unroll
            for (int ntp = 0; ntp < NT / 2; ++ntp) {
                unsigned B[4];
                ldsm_x4(B[0], B[1], B[2], B[3], b_base[ntp] + woff + s * 32);
                mma_tf32(acc[ntp * 2 + 0], A, B + 0);
                mma_tf32(acc[ntp * 2 + 1], A, B + 2);
            }
        }
    }

    // ---- epilogue ----
    const int g   = lane >> 2;
    const int tig = lane & 3;
    float bb[NT][2];
#pragma unroll
    for (int nt = 0; nt < NT; ++nt) {
        bb[nt][0] = bias[nt * 8 + 2 * tig];
        bb[nt][1] = bias[nt * 8 + 2 * tig + 1];
    }
    const int rbase = tile0 + warp * 16 + g;
#pragma unroll
    for (int half = 0; half < 2; ++half) {
        const int r = rbase + half * 8;
        if (r >= npts) continue;
#pragma unroll
        for (int nt = 0; nt < NT; ++nt) {
            float v0 = acc[nt][half * 2 + 0] + bb[nt][0];
            float v1 = acc[nt][half * 2 + 1] + bb[nt][1];
            if (RELU) { v0 = v0 > 0.f ? v0 : 0.f; v1 = v1 > 0.f ? v1 : 0.f; }
            if (ROUND_OUT) { v0 = rna_tf32(v0); v1 = rna_tf32(v1); }
            if (RESID) {
                const float2 rr = *(const float2*)(resid + (size_t)r * CCH + resid_off + nt * 8 + 2 * tig);
                v0 += rr.x; v1 += rr.y;
            }
            *(float2*)(fout + (size_t)r * out_stride + out_off + nt * 8 + 2 * tig)
                = make_float2(v0, v1);
        }
    }
}

// =====================================================================
// Dense 1x1 FFMA2 kernel (stage 4: 32->64 + residual, full precision).
// =====================================================================
template<int CIN, int COUT, int TP, bool RELU, bool RESID>
__global__ __launch_bounds__(256)
void conv1_kernel(const float* __restrict__ fin,
                  const float* __restrict__ W,
                  const float* __restrict__ bias,
                  float* __restrict__ fout, int out_stride, int out_off,
                  const float* __restrict__ resid, int resid_off,
                  int npts)
{
    constexpr int STR   = TP + 2;
    constexpr int CO_T  = COUT / 16;
    constexpr int PAIRS = TP / 32;
    constexpr int GTPR  = 256 / TP;
    constexpr int GCPT  = CIN / GTPR;

    extern __shared__ float smem[];
    float* sG = smem;
    float* sW = smem + CIN * STR;

    const int tid = threadIdx.x;
    const int n0  = blockIdx.x * TP;

    const int cg  = tid & 15;
    const int pg  = tid >> 4;
    const int co0 = cg * CO_T;
    const int p0  = pg * 2 * PAIRS;

    ull acc[PAIRS][CO_T];
#pragma unroll
    for (int i = 0; i < PAIRS; ++i)
#pragma unroll
        for (int c = 0; c < CO_T; ++c) acc[i][c] = 0ull;

    const int gp  = tid / GTPR;
    const int gh  = tid % GTPR;
    const int gn  = n0 + gp;
    const int ci0 = gh * GCPT;

    constexpr int W4 = CIN * COUT / 4;
    for (int i = tid; i < W4; i += 256) ((float4*)sW)[i] = ((const float4*)W)[i];

    if (gn < npts) {
        const float4* src = (const float4*)(fin + (size_t)gn * CIN + ci0);
#pragma unroll
        for (int c = 0; c < GCPT / 4; ++c) {
            float4 v = src[c];
            int cb = ci0 + c * 4;
            sG[(cb + 0) * STR + gp] = v.x;
            sG[(cb + 1) * STR + gp] = v.y;
            sG[(cb + 2) * STR + gp] = v.z;
            sG[(cb + 3) * STR + gp] = v.w;
        }
    } else {
#pragma unroll
        for (int c = 0; c < GCPT / 4; ++c) {
            int cb = ci0 + c * 4;
            sG[(cb + 0) * STR + gp] = 0.f;
            sG[(cb + 1) * STR + gp] = 0.f;
            sG[(cb + 2) * STR + gp] = 0.f;
            sG[(cb + 3) * STR + gp] = 0.f;
        }
    }
    __syncthreads();

#pragma unroll 4
    for (int ci = 0; ci < CIN; ++ci) {
        ull gg[PAIRS];
        const float* gr = sG + ci * STR + p0;
#pragma unroll
        for (int i = 0; i < PAIRS; ++i) gg[i] = *(const ull*)(gr + 2 * i);

        ull wd[CO_T];
        if (CO_T == 2) {
            float2 wv = *(const float2*)(sW + ci * COUT + co0);
            wd[0] = dup2(wv.x); wd[1] = dup2(wv.y);
        } else {
            float4 wv = *(const float4*)(sW + ci * COUT + co0);
            wd[0] = dup2(wv.x); wd[1] = dup2(wv.y);
            wd[2] = dup2(wv.z); wd[3] = dup2(wv.w);
        }
#pragma unroll
        for (int i = 0; i < PAIRS; ++i)
#pragma unroll
            for (int c = 0; c < CO_T; ++c)
                acc[i][c] = fma2(gg[i], wd[c], acc[i][c]);
    }

    float bb[CO_T];
#pragma unroll
    for (int c = 0; c < CO_T; ++c) bb[c] = bias[co0 + c];

#pragma unroll
    for (int i = 0; i < PAIRS; ++i) {
        float lo[CO_T], hi[CO_T];
#pragma unroll
        for (int c = 0; c < CO_T; ++c) unpack2(acc[i][c], lo[c], hi[c]);
#pragma unroll
        for (int e = 0; e < 2; ++e) {
            const int n = n0 + p0 + 2 * i + e;
            if (n >= npts) continue;
            float v[CO_T];
#pragma unroll
            for (int c = 0; c < CO_T; ++c) {
                v[c] = (e ? hi[c] : lo[c]) + bb[c];
                if (RELU) v[c] = v[c] > 0.f ? v[c] : 0.f;
            }
            if (RESID) {
                if (CO_T == 4) {
                    float4 r = *(const float4*)(resid + (size_t)n * CCH + resid_off + co0);
                    v[0] += r.x; v[1] += r.y; v[2] += r.z; v[3] += r.w;
                } else {
                    float2 r = *(const float2*)(resid + (size_t)n * CCH + resid_off + co0);
                    v[0] += r.x; v[1] += r.y;
                }
            }
            float* dst = fout + (size_t)n * out_stride + out_off + co0;
            if (CO_T == 4) {
                float4 st; st.x = v[0]; st.y = v[1]; st.z = v[2]; st.w = v[3];
                *(float4*)dst = st;
            } else {
                float2 st; st.x = v[0]; st.y = v[1];
                *(float2*)dst = st;
            }
        }
    }
}

// ---------- launch ----------
extern "C" void kernel_launch(void* const* d_in, const int* in_sizes, int n_in,
                              void* d_out, int out_size)
{
    const float* x    = (const float*)d_in[0];
    const int*   nbr  = (const int*)d_in[1];
    const int*   mask = (const int*)d_in[2];
    const float* W00 = (const float*)d_in[3];
    const float* b00 = (const float*)d_in[4];
    const float* W01 = (const float*)d_in[5];
    const float* b01 = (const float*)d_in[6];
    const float* W02 = (const float*)d_in[7];
    const float* b02 = (const float*)d_in[8];
    const float* W10 = (const float*)d_in[9];
    const float* b10 = (const float*)d_in[10];
    const float* W11 = (const float*)d_in[11];
    const float* b11 = (const float*)d_in[12];
    float* out = (float*)d_out;

    const int npts    = in_sizes[0] / CCH;
    const int grid128 = (npts + 127) / 128;

    float *h0p, *t0p, *h1p, *wt00, *wt01, *wt10, *wt11;
    unsigned* mbp;
    int* nbtp;
    cudaGetSymbolAddress((void**)&h0p,  g_h0);
    cudaGetSymbolAddress((void**)&t0p,  g_t0);
    cudaGetSymbolAddress((void**)&h1p,  g_h1);
    cudaGetSymbolAddress((void**)&mbp,  g_mbits);
    cudaGetSymbolAddress((void**)&nbtp, g_nbrT);
    cudaGetSymbolAddress((void**)&wt00, g_wt00);
    cudaGetSymbolAddress((void**)&wt01, g_wt01);
    cudaGetSymbolAddress((void**)&wt10, g_wt10);
    cudaGetSymbolAddress((void**)&wt11, g_wt11);

    // SMEM: NBUF * (128*36 + COUT*36) * 4
    const int smem_s1 = 2 * (128 * 36 + 32 * 36) * 4;   // 46080
    const int smem_s2 = 2 * (128 * 36 + 32 * 36) * 4;   // 46080
    const int smem_s3 = 2 * (128 * 36 + 32 * 36) * 4;   // 46080
    const int smem_s5 = 2 * (128 * 36 + 64 * 36) * 4;   // 55296
    const int smem_d4 = (32 * 130 + 32 * 64) * 4;       // 24832

    cudaFuncSetAttribute(conv3_tc<128, 32, 1, 2, true, true, true, false, true>,
                         cudaFuncAttributeMaxDynamicSharedMemorySize, smem_s1);
    cudaFuncSetAttribute(conv3_tc<32, 32, KTAPS, 2, false, false, true, false, false>,
                         cudaFuncAttributeMaxDynamicSharedMemorySize, smem_s2);
    cudaFuncSetAttribute(conv3_tc<128, 32, KTAPS, 2, false, true, true, false, true>,
                         cudaFuncAttributeMaxDynamicSharedMemorySize, smem_s3);
    cudaFuncSetAttribute(conv3_tc<32, 64, KTAPS, 2, false, false, false, true, false>,
                         cudaFuncAttributeMaxDynamicSharedMemorySize, smem_s5);

    // Launch order keeps stage 3 as the 4th launch (ncu-profiled).
    // [0] pack mask bits
    prep_mask<<<(npts + 255) / 256, 256>>>(mask, mbp, npts);
    // [1] transpose neighbor table
    {
        const size_t total = (size_t)npts * KTAPS;
        const int g = (int)((total + 255) / 256);
        prep_nbrT<<<g, 256>>>(nbr, nbtp, npts);
    }
    // [2] weights for stage 3
    prep_w<<<64, 256>>>(W10, wt10, KTAPS, CCH, C4);

    // [3] stage 3: h1 = round(relu(conv3(x, W10) + b10))  [tf32 mma, 128->32]
    conv3_tc<128, 32, KTAPS, 2, false, true, true, false, true><<<grid128, 256, smem_s3>>>(
        x, nbtp, mbp, wt10, b10, h1p, C4, 0, nullptr, 0, npts);

    // remaining weight preps
    prep_w<<<64, 256>>>(W00, wt00, 1,     CCH, C4);
    prep_w<<<64, 256>>>(W01, wt01, KTAPS, C4,  C4);
    prep_w<<<64, 256>>>(W11, wt11, KTAPS, C4,  C2);

    // stage 1: h0 = round(relu(x @ W00 + b00))            [tf32 mma, dense]
    conv3_tc<128, 32, 1, 2, true, true, true, false, true><<<grid128, 256, smem_s1>>>(
        x, nullptr, mbp, wt00, b00, h0p, C4, 0, nullptr, 0, npts);

    // stage 2: t0 = relu(conv3(h0, W01) + b01)            [tf32 mma, 32->32]
    conv3_tc<32, 32, KTAPS, 2, false, false, true, false, false><<<grid128, 256, smem_s2>>>(
        h0p, nbtp, mbp, wt01, b01, t0p, C4, 0, nullptr, 0, npts);

    // stage 4: out[:, 0:64] = t0 @ W02 + b02 + x[:, 0:64] [FFMA2]
    conv1_kernel<32, 64, 128, false, true><<<grid128, 256, smem_d4>>>(
        t0p, W02, b02, out, CCH, 0, x, 0, npts);

    // stage 5: out[:, 64:128] = conv3(h1, W11) + b11 + x[:, 64:]
    conv3_tc<32, 64, KTAPS, 2, false, false, false, true, false><<<grid128, 256, smem_s5>>>(
        h1p, nbtp, mbp, wt11, b11, out, CCH, 64, x, 64, npts);
}

// round 17
// speedup vs baseline: 1.4268x; 1.4268x over previous
#include <cuda_runtime.h>
#include <cuda_fp16.h>
#include <cstdint>

#define NPTS   500000
#define CCH    128
#define KTAPS  27
#define C4     32
#define C2     64

typedef unsigned long long ull;

// ---------- packed f32x2 helpers (dense FFMA stage 4) ----------
static __device__ __forceinline__ ull fma2(ull a, ull b, ull c) {
    ull d;
    asm("fma.rn.f32x2 %0, %1, %2, %3;" : "=l"(d) : "l"(a), "l"(b), "l"(c));
    return d;
}
static __device__ __forceinline__ ull dup2(float w) {
    ull r;
    asm("mov.b64 %0, {%1, %1};" : "=l"(r) : "f"(w));
    return r;
}
static __device__ __forceinline__ void unpack2(ull v, float& lo, float& hi) {
    asm("mov.b64 {%0, %1}, %2;" : "=f"(lo), "=f"(hi) : "l"(v));
}

// ---------- fp16 mma / ldmatrix / cp.async helpers ----------
static __device__ __forceinline__ void mma_f16(float* d, const unsigned* a, const unsigned* b) {
    asm volatile(
        "mma.sync.aligned.m16n8k16.row.col.f32.f16.f16.f32 "
        "{%0,%1,%2,%3},{%4,%5,%6,%7},{%8,%9},{%0,%1,%2,%3};"
        : "+f"(d[0]), "+f"(d[1]), "+f"(d[2]), "+f"(d[3])
        : "r"(a[0]), "r"(a[1]), "r"(a[2]), "r"(a[3]), "r"(b[0]), "r"(b[1]));
}
static __device__ __forceinline__ void ldsm_x4(unsigned& r0, unsigned& r1,
                                               unsigned& r2, unsigned& r3, unsigned addr) {
    asm volatile("ldmatrix.sync.aligned.m8n8.x4.shared.b16 {%0,%1,%2,%3}, [%4];"
                 : "=r"(r0), "=r"(r1), "=r"(r2), "=r"(r3) : "r"(addr));
}
static __device__ __forceinline__ void cp16(unsigned dst, const void* src, unsigned sz) {
    asm volatile("cp.async.cg.shared.global [%0], [%1], 16, %2;"
                 :: "r"(dst), "l"(src), "r"(sz));
}
static __device__ __forceinline__ void cp16f(unsigned dst, const void* src) {
    asm volatile("cp.async.cg.shared.global [%0], [%1], 16;"
                 :: "r"(dst), "l"(src));
}

// ---------- static scratch ----------
__device__ __half   g_x16[(size_t)NPTS * CCH];  // fp16 copy of x
__device__ __half   g_h0[(size_t)NPTS * C4];    // relu(x@W00+b00), fp16
__device__ __half   g_h1[(size_t)NPTS * C4];    // fp16
__device__ float    g_t0[(size_t)NPTS * C4];    // f32 (feeds FFMA stage 4)
__device__ unsigned g_mbits[NPTS];
__device__ int      g_nbrT[(size_t)KTAPS * NPTS];
__device__ __half   g_wt00[4   * C4 * 40];
__device__ __half   g_wt01[27  * C4 * 40];
__device__ __half   g_wt10[108 * C4 * 40];
__device__ __half   g_wt11[27  * C2 * 40];

// ---------- prep: x -> fp16 AND pack mask bits (one kernel) ----------
__global__ void prep_maskx(const float* __restrict__ x, const int* __restrict__ mask,
                           __half* __restrict__ x16, unsigned* __restrict__ mb, int npts)
{
    const size_t stride = (size_t)gridDim.x * blockDim.x;
    const size_t nel4 = (size_t)npts * CCH / 4;
    for (size_t i = (size_t)blockIdx.x * blockDim.x + threadIdx.x; i < nel4; i += stride) {
        float4 v = ((const float4*)x)[i];
        ((__half2*)x16)[2 * i + 0] = __floats2half2_rn(v.x, v.y);
        ((__half2*)x16)[2 * i + 1] = __floats2half2_rn(v.z, v.w);
    }
    for (size_t p = (size_t)blockIdx.x * blockDim.x + threadIdx.x; p < (size_t)npts; p += stride) {
        const int* mp = mask + p * KTAPS;
        unsigned b = 0;
#pragma unroll
        for (int k = 0; k < KTAPS; ++k) b |= (unsigned)(mp[k] != 0) << k;
        mb[p] = b;
    }
}

// ---------- neighbor transpose ----------
__global__ void prep_nbrT(const int* __restrict__ nbr, int* __restrict__ nbrT, int npts)
{
    const size_t total = (size_t)npts * KTAPS;
    for (size_t idx = (size_t)blockIdx.x * blockDim.x + threadIdx.x; idx < total;
         idx += (size_t)gridDim.x * blockDim.x) {
        const int p = (int)(idx % npts);
        const int k = (int)(idx / npts);
        nbrT[idx] = nbr[(size_t)p * KTAPS + k];
    }
}

// ---------- weight prep: fp16, [it][co][kh(40)] padded rows ----------
__global__ void prep_w16(const float* __restrict__ W, __half* __restrict__ Wt,
                         int ktaps, int CIN, int COUT)
{
    const int chunks = CIN / 32;
    const int total  = ktaps * chunks * COUT * 40;
    for (int idx = blockIdx.x * blockDim.x + threadIdx.x; idx < total;
         idx += gridDim.x * blockDim.x) {
        const int kh   = idx % 40;
        const int rest = idx / 40;
        const int co   = rest % COUT;
        const int kc   = rest / COUT;
        const int cc   = kc % chunks;
        const int k    = kc / chunks;
        __half v = __float2half_rn(0.f);
        if (kh < 32)
            v = __float2half_rn(W[((size_t)k * CIN + cc * 32 + kh) * COUT + co]);
        Wt[idx] = v;
    }
}

// =====================================================================
// fp16 tensor-core sparse/dense conv. 256 threads / 8 warps, 128 pts/blk,
// 1 m16-tile per warp, m16n8k16 mma (f32 accum), coalesced gather (4 lanes
// per row), single __syncthreads per iteration, NBUF cp.async ring.
// Row stride 40 halves (80B): conflict-free ldsm, 4-phase stores.
// =====================================================================
template<int CIN, int COUT, int KK, int NBUF, bool DENSE, bool RELU,
         bool RESID, bool OUTH>
__global__ __launch_bounds__(256)
void conv_h(const __half* __restrict__ fin,
            const int* __restrict__ nbrT,
            const unsigned* __restrict__ mbits_arr,
            const __half* __restrict__ Wt,
            const float* __restrict__ bias,
            void* __restrict__ fout_, int out_stride, int out_off,
            const float* __restrict__ resid, int resid_off,
            int npts)
{
    constexpr int CHUNKS = CIN / 32;
    constexpr int ITERS  = KK * CHUNKS;
    constexpr int NT     = COUT / 8;
    constexpr int GSTR   = 40;              // halves per row
    constexpr int G_ELE  = 128 * GSTR;      // halves
    constexpr int W_ELE  = COUT * GSTR;     // halves

    extern __shared__ float smem[];
    __half* sG = (__half*)smem;             // NBUF * G_ELE
    __half* sW = sG + NBUF * G_ELE;         // NBUF * W_ELE

    const int tid   = threadIdx.x;
    const int warp  = tid >> 5;
    const int lane  = tid & 31;
    const int tile0 = blockIdx.x * 128;

    const unsigned sg_u32 = (unsigned)__cvta_generic_to_shared(sG);
    const unsigned sw_u32 = (unsigned)__cvta_generic_to_shared(sW);

    // ---- gather: 4 lanes per row (16B each), warp owns its 16 rows ----
    const int grp = lane >> 2;    // 0..7 row subgroup
    const int sub = lane & 3;     // 16B slot
    int      pgl[2];
    int      jden[2];
    unsigned mcur[2];
    unsigned dstb[2];             // byte addr, buf 0
#pragma unroll
    for (int c = 0; c < 2; ++c) {
        const int rl = warp * 16 + c * 8 + grp;
        pgl[c]  = tile0 + rl;
        jden[c] = (pgl[c] < npts) ? pgl[c] : 0;
        mcur[c] = 0;
        if (!DENSE && pgl[c] < npts) mcur[c] = mbits_arr[pgl[c]];
        dstb[c] = sg_u32 + (unsigned)(rl * 80 + sub * 16);
    }

    // ---- incremental issue state ----
    int           cc_cur = 0;
    int           ccoff  = 0;          // halves
    const int*    nbrp   = nbrT;
    const __half* wsrc   = Wt;
    const __half* fin_s  = fin + sub * 8;

    auto issue = [&](int buf) {
#pragma unroll
        for (int c = 0; c < 2; ++c) {
            unsigned sz; int j;
            if (DENSE) {
                sz = (pgl[c] < npts) ? 16u : 0u;
                j  = jden[c];
            } else {
                const unsigned mb = mcur[c] & 1u;
                sz = mb ? 16u : 0u;
                j  = mb ? __ldg(nbrp + pgl[c]) : 0;
            }
            const __half* src = fin_s + (size_t)j * CIN + ccoff;
            cp16(dstb[c] + (unsigned)(buf * G_ELE * 2), src, sz);
        }
        // weights
        const unsigned wdst = sw_u32 + buf * W_ELE * 2;
        constexpr int NCH = W_ELE * 2 / 16;    // 16B chunks: 160 or 320
#pragma unroll
        for (int i = 0; i < (NCH + 255) / 256; ++i) {
            const int idx = tid + i * 256;
            if (NCH % 256 == 0 || idx < NCH)
                cp16f(wdst + idx * 16, wsrc + idx * 8);
        }
        wsrc += W_ELE;
        if (++cc_cur == CHUNKS) {
            cc_cur = 0; ccoff = 0;
            if (!DENSE) {
                nbrp += npts;
#pragma unroll
                for (int c = 0; c < 2; ++c) mcur[c] >>= 1;
            }
        } else {
            ccoff += 32;
        }
    };

    // ---- fragment base addresses (bytes) ----
    const int rowA = (lane & 7) + ((lane >> 3) & 1) * 8;
    const int colA = (lane >> 4) & 1;
    const unsigned a_base = sg_u32 + (unsigned)((warp * 16 + rowA) * 80 + colA * 16);

    const int rowB = (lane & 7) + ((lane >> 4) & 1) * 8;
    const int colB = (lane >> 3) & 1;
    unsigned b_base[NT / 2];
#pragma unroll
    for (int ntp = 0; ntp < NT / 2; ++ntp)
        b_base[ntp] = sw_u32 + (unsigned)((ntp * 16 + rowB) * 80 + colB * 16);

    float acc[NT][4];
#pragma unroll
    for (int nt = 0; nt < NT; ++nt)
#pragma unroll
        for (int i = 0; i < 4; ++i) acc[nt][i] = 0.f;

    // ---- pipeline ----
#pragma unroll
    for (int i = 0; i < NBUF - 1; ++i) {
        if (i < ITERS) issue(i);
        asm volatile("cp.async.commit_group;");
    }

    for (int it = 0; it < ITERS; ++it) {
        asm volatile("cp.async.wait_group %0;" :: "n"(NBUF - 2));
        __syncthreads();
        {
            const int nx = it + NBUF - 1;
            if (nx < ITERS) issue(nx % NBUF);
            asm volatile("cp.async.commit_group;");
        }
        const int buf = it % NBUF;
        const unsigned goff = (unsigned)(buf * G_ELE * 2);
        const unsigned woff = (unsigned)(buf * W_ELE * 2);
#pragma unroll
        for (int s = 0; s < 2; ++s) {          // two k16 steps per 32-chunk
            unsigned A[4];
            ldsm_x4(A[0], A[1], A[2], A[3], a_base + goff + s * 32);
#pragma unroll
            for (int ntp = 0; ntp < NT / 2; ++ntp) {
                unsigned B[4];
                ldsm_x4(B[0], B[1], B[2], B[3], b_base[ntp] + woff + s * 32);
                mma_f16(acc[ntp * 2 + 0], A, B + 0);
                mma_f16(acc[ntp * 2 + 1], A, B + 2);
            }
        }
    }

    // ---- epilogue ----
    const int g   = lane >> 2;
    const int tig = lane & 3;
    float bb[NT][2];
#pragma unroll
    for (int nt = 0; nt < NT; ++nt) {
        bb[nt][0] = bias[nt * 8 + 2 * tig];
        bb[nt][1] = bias[nt * 8 + 2 * tig + 1];
    }
    const int rbase = tile0 + warp * 16 + g;
#pragma unroll
    for (int half = 0; half < 2; ++half) {
        const int r = rbase + half * 8;
        if (r >= npts) continue;
#pragma unroll
        for (int nt = 0; nt < NT; ++nt) {
            float v0 = acc[nt][half * 2 + 0] + bb[nt][0];
            float v1 = acc[nt][half * 2 + 1] + bb[nt][1];
            if (RELU) { v0 = v0 > 0.f ? v0 : 0.f; v1 = v1 > 0.f ? v1 : 0.f; }
            if (OUTH) {
                __half2* dst = (__half2*)((__half*)fout_ + (size_t)r * out_stride
                                          + out_off + nt * 8 + 2 * tig);
                *dst = __floats2half2_rn(v0, v1);
            } else {
                if (RESID) {
                    const float2 rr = *(const float2*)(resid + (size_t)r * CCH + resid_off + nt * 8 + 2 * tig);
                    v0 += rr.x; v1 += rr.y;
                }
                *(float2*)((float*)fout_ + (size_t)r * out_stride + out_off + nt * 8 + 2 * tig)
                    = make_float2(v0, v1);
            }
        }
    }
}

// =====================================================================
// Dense 1x1 FFMA2 kernel (stage 4: 32->64 + residual, full precision).
// =====================================================================
template<int CIN, int COUT, int TP, bool RELU, bool RESID>
__global__ __launch_bounds__(256)
void conv1_kernel(const float* __restrict__ fin,
                  const float* __restrict__ W,
                  const float* __restrict__ bias,
                  float* __restrict__ fout, int out_stride, int out_off,
                  const float* __restrict__ resid, int resid_off,
                  int npts)
{
    constexpr int STR   = TP + 2;
    constexpr int CO_T  = COUT / 16;
    constexpr int PAIRS = TP / 32;
    constexpr int GTPR  = 256 / TP;
    constexpr int GCPT  = CIN / GTPR;

    extern __shared__ float smem[];
    float* sG = smem;
    float* sW = smem + CIN * STR;

    const int tid = threadIdx.x;
    const int n0  = blockIdx.x * TP;

    const int cg  = tid & 15;
    const int pg  = tid >> 4;
    const int co0 = cg * CO_T;
    const int p0  = pg * 2 * PAIRS;

    ull acc[PAIRS][CO_T];
#pragma unroll
    for (int i = 0; i < PAIRS; ++i)
#pragma unroll
        for (int c = 0; c < CO_T; ++c) acc[i][c] = 0ull;

    const int gp  = tid / GTPR;
    const int gh  = tid % GTPR;
    const int gn  = n0 + gp;
    const int ci0 = gh * GCPT;

    constexpr int W4 = CIN * COUT / 4;
    for (int i = tid; i < W4; i += 256) ((float4*)sW)[i] = ((const float4*)W)[i];

    if (gn < npts) {
        const float4* src = (const float4*)(fin + (size_t)gn * CIN + ci0);
#pragma unroll
        for (int c = 0; c < GCPT / 4; ++c) {
            float4 v = src[c];
            int cb = ci0 + c * 4;
            sG[(cb + 0) * STR + gp] = v.x;
            sG[(cb + 1) * STR + gp] = v.y;
            sG[(cb + 2) * STR + gp] = v.z;
            sG[(cb + 3) * STR + gp] = v.w;
        }
    } else {
#pragma unroll
        for (int c = 0; c < GCPT / 4; ++c) {
            int cb = ci0 + c * 4;
            sG[(cb + 0) * STR + gp] = 0.f;
            sG[(cb + 1) * STR + gp] = 0.f;
            sG[(cb + 2) * STR + gp] = 0.f;
            sG[(cb + 3) * STR + gp] = 0.f;
        }
    }
    __syncthreads();

#pragma unroll 4
    for (int ci = 0; ci < CIN; ++ci) {
        ull gg[PAIRS];
        const float* gr = sG + ci * STR + p0;
#pragma unroll
        for (int i = 0; i < PAIRS; ++i) gg[i] = *(const ull*)(gr + 2 * i);

        ull wd[CO_T];
        if (CO_T == 2) {
            float2 wv = *(const float2*)(sW + ci * COUT + co0);
            wd[0] = dup2(wv.x); wd[1] = dup2(wv.y);
        } else {
            float4 wv = *(const float4*)(sW + ci * COUT + co0);
            wd[0] = dup2(wv.x); wd[1] = dup2(wv.y);
            wd[2] = dup2(wv.z); wd[3] = dup2(wv.w);
        }
#pragma unroll
        for (int i = 0; i < PAIRS; ++i)
#pragma unroll
            for (int c = 0; c < CO_T; ++c)
                acc[i][c] = fma2(gg[i], wd[c], acc[i][c]);
    }

    float bb[CO_T];
#pragma unroll
    for (int c = 0; c < CO_T; ++c) bb[c] = bias[co0 + c];

#pragma unroll
    for (int i = 0; i < PAIRS; ++i) {
        float lo[CO_T], hi[CO_T];
#pragma unroll
        for (int c = 0; c < CO_T; ++c) unpack2(acc[i][c], lo[c], hi[c]);
#pragma unroll
        for (int e = 0; e < 2; ++e) {
            const int n = n0 + p0 + 2 * i + e;
            if (n >= npts) continue;
            float v[CO_T];
#pragma unroll
            for (int c = 0; c < CO_T; ++c) {
                v[c] = (e ? hi[c] : lo[c]) + bb[c];
                if (RELU) v[c] = v[c] > 0.f ? v[c] : 0.f;
            }
            if (RESID) {
                if (CO_T == 4) {
                    float4 r = *(const float4*)(resid + (size_t)n * CCH + resid_off + co0);
                    v[0] += r.x; v[1] += r.y; v[2] += r.z; v[3] += r.w;
                } else {
                    float2 r = *(const float2*)(resid + (size_t)n * CCH + resid_off + co0);
                    v[0] += r.x; v[1] += r.y;
                }
            }
            float* dst = fout + (size_t)n * out_stride + out_off + co0;
            if (CO_T == 4) {
                float4 st; st.x = v[0]; st.y = v[1]; st.z = v[2]; st.w = v[3];
                *(float4*)dst = st;
            } else {
                float2 st; st.x = v[0]; st.y = v[1];
                *(float2*)dst = st;
            }
        }
    }
}

// ---------- launch ----------
extern "C" void kernel_launch(void* const* d_in, const int* in_sizes, int n_in,
                              void* d_out, int out_size)
{
    const float* x    = (const float*)d_in[0];
    const int*   nbr  = (const int*)d_in[1];
    const int*   mask = (const int*)d_in[2];
    const float* W00 = (const float*)d_in[3];
    const float* b00 = (const float*)d_in[4];
    const float* W01 = (const float*)d_in[5];
    const float* b01 = (const float*)d_in[6];
    const float* W02 = (const float*)d_in[7];
    const float* b02 = (const float*)d_in[8];
    const float* W10 = (const float*)d_in[9];
    const float* b10 = (const float*)d_in[10];
    const float* W11 = (const float*)d_in[11];
    const float* b11 = (const float*)d_in[12];
    float* out = (float*)d_out;

    const int npts    = in_sizes[0] / CCH;
    const int grid128 = (npts + 127) / 128;

    __half *x16p, *h0p, *h1p, *wt00, *wt01, *wt10, *wt11;
    float *t0p;
    unsigned* mbp;
    int* nbtp;
    cudaGetSymbolAddress((void**)&x16p, g_x16);
    cudaGetSymbolAddress((void**)&h0p,  g_h0);
    cudaGetSymbolAddress((void**)&h1p,  g_h1);
    cudaGetSymbolAddress((void**)&t0p,  g_t0);
    cudaGetSymbolAddress((void**)&mbp,  g_mbits);
    cudaGetSymbolAddress((void**)&nbtp, g_nbrT);
    cudaGetSymbolAddress((void**)&wt00, g_wt00);
    cudaGetSymbolAddress((void**)&wt01, g_wt01);
    cudaGetSymbolAddress((void**)&wt10, g_wt10);
    cudaGetSymbolAddress((void**)&wt11, g_wt11);

    // SMEM (bytes): NBUF * (128*40 + COUT*40) * 2
    const int smem_s1 = 2 * (128 * 40 + 32 * 40) * 2;   // 25600
    const int smem_s2 = 3 * (128 * 40 + 32 * 40) * 2;   // 38400
    const int smem_s3 = 3 * (128 * 40 + 32 * 40) * 2;   // 38400
    const int smem_s5 = 3 * (128 * 40 + 64 * 40) * 2;   // 46080
    const int smem_d4 = (32 * 130 + 32 * 64) * 4;       // 24832

    cudaFuncSetAttribute(conv_h<128, 32, 1, 2, true, true, false, true>,
                         cudaFuncAttributeMaxDynamicSharedMemorySize, smem_s1);
    cudaFuncSetAttribute(conv_h<32, 32, KTAPS, 3, false, true, false, false>,
                         cudaFuncAttributeMaxDynamicSharedMemorySize, smem_s2);
    cudaFuncSetAttribute(conv_h<128, 32, KTAPS, 3, false, true, false, true>,
                         cudaFuncAttributeMaxDynamicSharedMemorySize, smem_s3);
    cudaFuncSetAttribute(conv_h<32, 64, KTAPS, 3, false, false, true, false>,
                         cudaFuncAttributeMaxDynamicSharedMemorySize, smem_s5);

    // Launch order keeps stage 3 as the 4th launch (ncu-profiled).
    // [0] x -> fp16 + pack mask bits
    prep_maskx<<<2048, 256>>>(x, mask, x16p, mbp, npts);
    // [1] transpose neighbor table
    {
        const size_t total = (size_t)npts * KTAPS;
        const int g = (int)((total + 255) / 256);
        prep_nbrT<<<g, 256>>>(nbr, nbtp, npts);
    }
    // [2] weights for stage 3
    prep_w16<<<64, 256>>>(W10, wt10, KTAPS, CCH, C4);

    // [3] stage 3: h1 = fp16(relu(conv3(x16, W10) + b10))  [fp16 mma, 128->32]
    conv_h<128, 32, KTAPS, 3, false, true, false, true><<<grid128, 256, smem_s3>>>(
        x16p, nbtp, mbp, wt10, b10, h1p, C4, 0, nullptr, 0, npts);

    // remaining weight preps
    prep_w16<<<64, 256>>>(W00, wt00, 1,     CCH, C4);
    prep_w16<<<64, 256>>>(W01, wt01, KTAPS, C4,  C4);
    prep_w16<<<64, 256>>>(W11, wt11, KTAPS, C4,  C2);

    // stage 1: h0 = fp16(relu(x16 @ W00 + b00))            [fp16 mma, dense]
    conv_h<128, 32, 1, 2, true, true, false, true><<<grid128, 256, smem_s1>>>(
        x16p, nullptr, mbp, wt00, b00, h0p, C4, 0, nullptr, 0, npts);

    // stage 2: t0 = relu(conv3(h0, W01) + b01)  (f32 out)  [fp16 mma, 32->32]
    conv_h<32, 32, KTAPS, 3, false, true, false, false><<<grid128, 256, smem_s2>>>(
        h0p, nbtp, mbp, wt01, b01, t0p, C4, 0, nullptr, 0, npts);

    // stage 4: out[:, 0:64] = t0 @ W02 + b02 + x[:, 0:64]  [FFMA2, f32]
    conv1_kernel<32, 64, 128, false, true><<<grid128, 256, smem_d4>>>(
        t0p, W02, b02, out, CCH, 0, x, 0, npts);

    // stage 5: out[:, 64:128] = conv3(h1, W11) + b11 + x[:, 64:]  [fp16 mma]
    conv_h<32, 64, KTAPS, 3, false, false, true, false><<<grid128, 256, smem_s5>>>(
        h1p, nbtp, mbp, wt11, b11, out, CCH, 64, x, 64, npts);
}